// round 16
// baseline (speedup 1.0000x reference)
#include <cuda_runtime.h>
#include <cuda_fp16.h>
#include <mma.h>
#include <math.h>
#include <cstdint>

using namespace nvcuda;

#define SEQ   2048
#define HID   1024
#define NTOK  1024
#define NHEAD 16
#define HDIM  64

typedef __half f16;

// ---------------- scratch (device globals; no runtime allocation) ----------
__device__ f16 g_pre[3 * SEQ * NTOK];          // pre-gelu logits (fp16)
__device__ f16 g_attn[3 * SEQ * NTOK];         // gelu out (fp16, GEMM A)
__device__ f16 g_x16[SEQ * HID];
__device__ f16 g_ctx16[SEQ * HID];
__device__ f16 g_wf[8][NTOK * HID];            // weights fp16 (GEMM B)
__device__ f16 g_qkv[3 * SEQ * HID];           // q(scaled) | k | v  (fp16)

// ---------------- small helpers -------------------------------------------
__device__ __forceinline__ unsigned short f2u(f16 h) {
    return *reinterpret_cast<unsigned short*>(&h);
}
__device__ __forceinline__ unsigned pf2(f16 a, f16 b) {
    return (unsigned)f2u(a) | ((unsigned)f2u(b) << 16);
}
__device__ __forceinline__ void cpa16(void* smem, const void* gmem) {
    unsigned s = (unsigned)__cvta_generic_to_shared(smem);
    asm volatile("cp.async.cg.shared.global [%0], [%1], 16;" :: "r"(s), "l"(gmem));
}
#define CPA_COMMIT() asm volatile("cp.async.commit_group;")
#define CPA_WAIT(n)  asm volatile("cp.async.wait_group %0;" :: "n"(n))

// ---------------- conversions ----------------------------------------------
__global__ void __launch_bounds__(256) cvt_f16(const float* __restrict__ in,
                                               f16* __restrict__ o)
{
    int i = (blockIdx.x * 256 + threadIdx.x) * 4;
    float4 v = *(const float4*)(in + i);
    uint2 u;
    u.x = pf2(__float2half_rn(v.x), __float2half_rn(v.y));
    u.y = pf2(__float2half_rn(v.z), __float2half_rn(v.w));
    *(uint2*)(o + i) = u;
}

struct W8 { const float* src[8]; };

__global__ void __launch_bounds__(256) cvt_w8(W8 s, f16* __restrict__ w)
{
    const size_t WSZ = (size_t)NTOK * HID;
    int z = blockIdx.y;
    int i = (blockIdx.x * 256 + threadIdx.x) * 4;
    float4 v = *(const float4*)(s.src[z] + i);
    uint2 o;
    o.x = pf2(__float2half_rn(v.x), __float2half_rn(v.y));
    o.y = pf2(__float2half_rn(v.z), __float2half_rn(v.w));
    *(uint2*)(w + z * WSZ + i) = o;
}

// ---------------- tensor GEMM (pure fp16, 1 term, no split-K) --------------
//  BT=true : B is [N,K] row-major (C = A*B^T);  BT=false: B is [K,N]
//  F16OUT : scaled fp16 output straight from fragments; else fp32.
//  128x128 tile, BK=32, 256 threads (8 warps 4x2, warp tile 32x64).
struct GBF {
    const f16 *A[3], *B[3];
    float* C[3];
    f16* O[3];
    float scale[3];
};

#define ASZ 5120                       // 128*40 elems
#define BSZ_BT 5120                    // 128*40 elems
#define BSZ_NBT 4352                   // 32*136 elems
#define GEMM_SMEM_BT  ((2 * ASZ + 2 * BSZ_BT) * 2)    // 40960 bytes
#define GEMM_SMEM_BN  ((2 * ASZ + 2 * BSZ_NBT) * 2)   // 37888 bytes

template <bool BT, bool F16OUT>
__global__ void __launch_bounds__(256, 2) tgemm_f16(GBF p, int M, int N, int K)
{
    constexpr int BSZ = BT ? BSZ_BT : BSZ_NBT;

    extern __shared__ f16 dyn[];
    f16* As = dyn;                         // [2][ASZ]
    f16* Bs = dyn + 2 * ASZ;               // [2][BSZ]

    const int zi = blockIdx.z;
    const f16* __restrict__ A = p.A[zi];
    const f16* __restrict__ B = p.B[zi];

    const int tid = threadIdx.x;
    const int bx = blockIdx.x;
    const int by = blockIdx.y;
    const int wid = tid >> 5;
    const int wm = wid & 3;
    const int wn = wid >> 2;

    wmma::fragment<wmma::accumulator, 16, 16, 16, float> cf[2][4];
#pragma unroll
    for (int mi = 0; mi < 2; mi++)
#pragma unroll
        for (int ni = 0; ni < 4; ni++) wmma::fill_fragment(cf[mi][ni], 0.f);

    int arow[2], akq[2], bkr[2], bnq[2];
#pragma unroll
    for (int i = 0; i < 2; i++) {
        int c = tid + i * 256;
        arow[i] = c >> 2;  akq[i] = (c & 3) * 8;
        if (BT) { bkr[i] = c >> 2;  bnq[i] = (c & 3) * 8; }
        else    { bkr[i] = c >> 4;  bnq[i] = (c & 15) * 8; }
    }

    const int T = K / 32;

    auto stage = [&](int t, int b) {
        const int kt = t * 32;
#pragma unroll
        for (int i = 0; i < 2; i++) {
            cpa16(As + b * ASZ + arow[i] * 40 + akq[i],
                  A + (size_t)(by * 128 + arow[i]) * K + kt + akq[i]);
            if (BT) {
                cpa16(Bs + b * BSZ + bkr[i] * 40 + bnq[i],
                      B + (size_t)(bx * 128 + bkr[i]) * K + kt + bnq[i]);
            } else {
                cpa16(Bs + b * BSZ + bkr[i] * 136 + bnq[i],
                      B + (size_t)(kt + bkr[i]) * N + bx * 128 + bnq[i]);
            }
        }
        CPA_COMMIT();
    };

    stage(0, 0);

    for (int t = 0; t < T; t++) {
        const int b = t & 1;
        CPA_WAIT(0);
        __syncthreads();
        if (t + 1 < T) stage(t + 1, b ^ 1);

        const f16* as_p = As + b * ASZ;
        const f16* bs_p = Bs + b * BSZ;

#pragma unroll
        for (int kk = 0; kk < 2; kk++) {
            wmma::fragment<wmma::matrix_a, 16, 16, 16, f16,
                           wmma::row_major> af[2];
#pragma unroll
            for (int mi = 0; mi < 2; mi++)
                wmma::load_matrix_sync(af[mi], as_p + (wm * 32 + mi * 16) * 40 + kk * 16, 40);
            if (BT) {
                wmma::fragment<wmma::matrix_b, 16, 16, 16, f16,
                               wmma::col_major> bfr[4];
#pragma unroll
                for (int ni = 0; ni < 4; ni++)
                    wmma::load_matrix_sync(bfr[ni], bs_p + (wn * 64 + ni * 16) * 40 + kk * 16, 40);
#pragma unroll
                for (int mi = 0; mi < 2; mi++)
#pragma unroll
                    for (int ni = 0; ni < 4; ni++)
                        wmma::mma_sync(cf[mi][ni], af[mi], bfr[ni], cf[mi][ni]);
            } else {
                wmma::fragment<wmma::matrix_b, 16, 16, 16, f16,
                               wmma::row_major> bfr[4];
#pragma unroll
                for (int ni = 0; ni < 4; ni++)
                    wmma::load_matrix_sync(bfr[ni], bs_p + kk * 16 * 136 + wn * 64 + ni * 16, 136);
#pragma unroll
                for (int mi = 0; mi < 2; mi++)
#pragma unroll
                    for (int ni = 0; ni < 4; ni++)
                        wmma::mma_sync(cf[mi][ni], af[mi], bfr[ni], cf[mi][ni]);
            }
        }
    }

    if (F16OUT) {
        const float sc = p.scale[zi];
        f16* __restrict__ O = p.O[zi];
#pragma unroll
        for (int mi = 0; mi < 2; mi++)
#pragma unroll
            for (int ni = 0; ni < 4; ni++) {
                wmma::fragment<wmma::accumulator, 16, 16, 16, __half> hf;
#pragma unroll
                for (int e = 0; e < hf.num_elements; e++)
                    hf.x[e] = __float2half_rn(cf[mi][ni].x[e] * sc);
                f16* Op = O + (size_t)(by * 128 + wm * 32 + mi * 16) * N
                            + bx * 128 + wn * 64 + ni * 16;
                wmma::store_matrix_sync(Op, hf, N, wmma::mem_row_major);
            }
    } else {
        float* __restrict__ C = p.C[zi];
#pragma unroll
        for (int mi = 0; mi < 2; mi++)
#pragma unroll
            for (int ni = 0; ni < 4; ni++) {
                float* Cp = C + (size_t)(by * 128 + wm * 32 + mi * 16) * N
                              + bx * 128 + wn * 64 + ni * 16;
                wmma::store_matrix_sync(Cp, cf[mi][ni], N, wmma::mem_row_major);
            }
    }
}

// ---------------- gelu + L2-norm (fp16 in, fp16 out, fp32 math) ------------
__global__ void __launch_bounds__(256) gelu_l2norm_cvt(const f16* __restrict__ pre,
                                                       f16* __restrict__ o)
{
    const int row = blockIdx.x;
    const int tid = threadIdx.x;
    __shared__ float g[NTOK];
    __shared__ float ws[8];

    const f16* p0 = pre + (size_t)row * NTOK;

    float ss = 0.f;
    for (int i = tid; i < NTOK; i += 256) {
        float v = __half2float(p0[i]);
        float gv = 0.5f * v * (1.f + erff(v * 0.70710678118654752f));
        g[i] = gv;
        ss += gv * gv;
    }
#pragma unroll
    for (int of = 16; of > 0; of >>= 1) ss += __shfl_xor_sync(0xffffffffu, ss, of);
    if ((tid & 31) == 0) ws[tid >> 5] = ss;
    __syncthreads();

    float tot = 0.f;
#pragma unroll
    for (int w = 0; w < 8; w++) tot += ws[w];

    const float sc = 32.f * rsqrtf(tot);
    for (int i = tid; i < NTOK; i += 256)
        o[(size_t)row * NTOK + i] = __float2half_rn(g[i] * sc);
}

// ---------------- tensor-core causal flash attention (fp16, 1-term) -------
#define FPAD 72
#define SPAD 68

__global__ void __launch_bounds__(256) flash_tc(const f16* __restrict__ qkv,
                                                f16* __restrict__ ctx)
{
    const size_t SZ = (size_t)SEQ * HID;
    const int tid  = threadIdx.x;
    const int wid  = tid >> 5;
    const int head = blockIdx.y;
    const int qt   = gridDim.x - 1 - blockIdx.x;   // heavy tiles first
    const int hc   = head * HDIM;

    extern __shared__ char dynb[];
    f16*   Qs  = (f16*)dynb;                        // [128][72]
    f16*   KVs = Qs + 128 * FPAD;                   // [2 buf][2 arr][64*72]
    float* S   = (float*)(KVs + 2 * 2 * 64 * FPAD); // [128][68]
    float* O   = S + 128 * SPAD;                    // [128][68]
    f16*   Ps  = (f16*)(O + 128 * SPAD);            // [128][72]

    const int myrow  = tid >> 1;
    const int myhalf = tid & 1;
    float m_reg = -1e30f, l_reg = 0.f;

    {
        float* Orow = O + myrow * SPAD + myhalf * 32;
#pragma unroll
        for (int j = 0; j < 32; j += 4)
            *(float4*)(Orow + j) = make_float4(0.f, 0.f, 0.f, 0.f);
    }

    for (int i = tid; i < 1024; i += 256) {
        int r = i >> 3, c8 = (i & 7) * 8;
        cpa16(Qs + r * FPAD + c8, qkv + (size_t)(qt * 128 + r) * HID + hc + c8);
    }
    CPA_COMMIT();

    auto stageKV = [&](int step, int buf) {
        const int kb = step * 64;
        f16* base = KVs + buf * (2 * 64 * FPAD);
        for (int i = tid; i < 512; i += 256) {
            int r = i >> 3, c8 = (i & 7) * 8;
            size_t g = (size_t)(kb + r) * HID + hc + c8;
            cpa16(base + 0 * 64 * FPAD + r * FPAD + c8, qkv + SZ + g);       // K
            cpa16(base + 1 * 64 * FPAD + r * FPAD + c8, qkv + 2 * SZ + g);   // V
        }
        CPA_COMMIT();
    };

    const int nsteps = 2 * qt + 2;
    stageKV(0, 0);

    const int wq = wid * 16;

    for (int step = 0; step < nsteps; step++) {
        const int buf = step & 1;
        const int kb  = step * 64;
        CPA_WAIT(0);
        __syncthreads();
        if (step + 1 < nsteps) stageKV(step + 1, buf ^ 1);

        const f16* kf = KVs + buf * (2 * 64 * FPAD);
        const f16* vf = kf + 64 * FPAD;

        // ---- QK^T -> S[128][64] ----
        {
            wmma::fragment<wmma::matrix_a, 16, 16, 16, f16, wmma::row_major> qa[4];
#pragma unroll
            for (int ks = 0; ks < 4; ks++)
                wmma::load_matrix_sync(qa[ks], Qs + wq * FPAD + ks * 16, FPAD);
#pragma unroll
            for (int nf = 0; nf < 4; nf++) {
                wmma::fragment<wmma::accumulator, 16, 16, 16, float> acc;
                wmma::fill_fragment(acc, 0.f);
#pragma unroll
                for (int ks = 0; ks < 4; ks++) {
                    wmma::fragment<wmma::matrix_b, 16, 16, 16, f16, wmma::col_major> bk;
                    wmma::load_matrix_sync(bk, kf + nf * 16 * FPAD + ks * 16, FPAD);
                    wmma::mma_sync(acc, qa[ks], bk, acc);
                }
                wmma::store_matrix_sync(S + wq * SPAD + nf * 16, acc, SPAD,
                                        wmma::mem_row_major);
            }
        }
        __syncthreads();

        // ---- online softmax: 2 threads per row ----
        {
            const int qrow = qt * 128 + myrow;
            int jmax = qrow - kb + 1;
            if (jmax > 64) jmax = 64;
            const int base = myhalf * 32;
            const float* Srow = S + myrow * SPAD + base;
            unsigned* pp = (unsigned*)(Ps + myrow * FPAD) + myhalf * 16;

            float lmax = -1e30f;
#pragma unroll
            for (int j = 0; j < 32; j++)
                if (base + j < jmax) lmax = fmaxf(lmax, Srow[j]);
            float omax = __shfl_xor_sync(0xffffffffu, lmax, 1);
            float tmax = fmaxf(lmax, omax);

            const bool active = (jmax > 0);
            float mnew = active ? fmaxf(m_reg, tmax) : m_reg;
            float corr = __expf(m_reg - mnew);

            float suml = 0.f;
#pragma unroll
            for (int j2 = 0; j2 < 16; j2++) {
                int ja = base + 2 * j2;
                float pa = (ja < jmax)     ? __expf(Srow[2 * j2]     - mnew) : 0.f;
                float pb = (ja + 1 < jmax) ? __expf(Srow[2 * j2 + 1] - mnew) : 0.f;
                suml += pa + pb;
                pp[j2] = pf2(__float2half_rn(pa), __float2half_rn(pb));
            }
            float osum = __shfl_xor_sync(0xffffffffu, suml, 1);
            l_reg = l_reg * corr + suml + osum;
            m_reg = mnew;

            float* Orow = O + myrow * SPAD + base;
#pragma unroll
            for (int j = 0; j < 32; j += 4) {
                float4 v = *(float4*)(Orow + j);
                *(float4*)(Orow + j) = make_float4(v.x * corr, v.y * corr,
                                                   v.z * corr, v.w * corr);
            }
        }
        __syncthreads();

        // ---- P*V accumulated into O ----
        {
            wmma::fragment<wmma::matrix_a, 16, 16, 16, f16, wmma::row_major> pa[4];
#pragma unroll
            for (int ks = 0; ks < 4; ks++)
                wmma::load_matrix_sync(pa[ks], Ps + wq * FPAD + ks * 16, FPAD);
#pragma unroll
            for (int nf = 0; nf < 4; nf++) {
                wmma::fragment<wmma::accumulator, 16, 16, 16, float> acc;
                wmma::load_matrix_sync(acc, O + wq * SPAD + nf * 16, SPAD,
                                       wmma::mem_row_major);
#pragma unroll
                for (int ks = 0; ks < 4; ks++) {
                    wmma::fragment<wmma::matrix_b, 16, 16, 16, f16, wmma::row_major> bv;
                    wmma::load_matrix_sync(bv, vf + ks * 16 * FPAD + nf * 16, FPAD);
                    wmma::mma_sync(acc, pa[ks], bv, acc);
                }
                wmma::store_matrix_sync(O + wq * SPAD + nf * 16, acc, SPAD,
                                        wmma::mem_row_major);
            }
        }
    }

    __syncthreads();

    // epilogue: O/l -> ctx fp16
    {
        const float invl = 1.f / l_reg;
        const float* Orow = O + myrow * SPAD + myhalf * 32;
        size_t gbase = (size_t)(qt * 128 + myrow) * HID + hc + myhalf * 32;
#pragma unroll
        for (int j = 0; j < 32; j++)
            ctx[gbase + j] = __float2half_rn(Orow[j] * invl);
    }
}

#define FLASH_SMEM (128*FPAD*2 + 2*2*64*FPAD*2 + 2*128*SPAD*4 + 128*FPAD*2 + 128)

// ---------------------------------------------------------------------------
extern "C" void kernel_launch(void* const* d_in, const int* in_sizes, int n_in,
                              void* d_out, int out_size)
{
    const float* x = (const float*)d_in[0];
    float* out = (float*)d_out;

    f16 *pre, *attn, *x16, *ctx16, *wf, *qkv;
    cudaGetSymbolAddress((void**)&pre, g_pre);
    cudaGetSymbolAddress((void**)&attn, g_attn);
    cudaGetSymbolAddress((void**)&x16, g_x16);
    cudaGetSymbolAddress((void**)&ctx16, g_ctx16);
    cudaGetSymbolAddress((void**)&wf, g_wf);
    cudaGetSymbolAddress((void**)&qkv, g_qkv);

    cudaFuncSetAttribute(tgemm_f16<true, true>,
                         cudaFuncAttributeMaxDynamicSharedMemorySize, GEMM_SMEM_BT);
    cudaFuncSetAttribute(tgemm_f16<false, true>,
                         cudaFuncAttributeMaxDynamicSharedMemorySize, GEMM_SMEM_BN);
    cudaFuncSetAttribute(tgemm_f16<false, false>,
                         cudaFuncAttributeMaxDynamicSharedMemorySize, GEMM_SMEM_BN);
    cudaFuncSetAttribute(flash_tc,
                         cudaFuncAttributeMaxDynamicSharedMemorySize, FLASH_SMEM);

    const size_t WSZ = (size_t)NTOK * HID;
    const size_t AS  = (size_t)SEQ * NTOK;
    const size_t SZ  = (size_t)SEQ * HID;

    // convert inputs (single fp16)
    cvt_f16<<<SEQ * HID / 1024, 256>>>(x, x16);
    W8 w8;
    for (int i = 0; i < 8; i++) w8.src[i] = (const float*)d_in[1 + i];
    cvt_w8<<<dim3(WSZ / 1024, 8), 256>>>(w8, wf);

    // ---- QKV pattention GEMM1 (x @ keys^T), batched, fp16 out ----
    GBF p1 = {};
    for (int z = 0; z < 3; z++) {
        p1.A[z] = x16;
        p1.B[z] = wf + (size_t)(z * 2) * WSZ;   // qk,kk,vk
        p1.O[z] = pre + z * AS;
        p1.scale[z] = 1.f;
    }
    tgemm_f16<true, true><<<dim3(8, 16, 3), 256, GEMM_SMEM_BT>>>(p1, SEQ, NTOK, HID);

    gelu_l2norm_cvt<<<3 * SEQ, 256>>>(pre, attn);

    // ---- GEMM2 (w @ vals), fused scaled-fp16 epilogue -> qkv ----
    GBF p2 = {};
    for (int z = 0; z < 3; z++) {
        p2.A[z] = attn + z * AS;
        p2.B[z] = wf + (size_t)(z * 2 + 1) * WSZ;   // qv,kv,vv
        p2.O[z] = qkv + z * SZ;
        p2.scale[z] = (z == 0) ? 0.125f : 1.f;
    }
    tgemm_f16<false, true><<<dim3(8, 16, 3), 256, GEMM_SMEM_BN>>>(p2, SEQ, HID, NTOK);

    // ---- tensor-core causal attention (fp16 1-term) -> ctx fp16 ----
    flash_tc<<<dim3(SEQ / 128, NHEAD), 256, FLASH_SMEM>>>(qkv, ctx16);

    // ---- output projection: GEMM3 fp16 out -> gelu -> GEMM4 fp32 out ----
    GBF p3 = {};
    p3.A[0] = ctx16;
    p3.B[0] = wf + (size_t)6 * WSZ;   // pk
    p3.O[0] = pre;
    p3.scale[0] = 1.f;
    tgemm_f16<true, true><<<dim3(8, 16, 1), 256, GEMM_SMEM_BT>>>(p3, SEQ, NTOK, HID);

    gelu_l2norm_cvt<<<SEQ, 256>>>(pre, attn);

    GBF p4 = {};
    p4.A[0] = attn;
    p4.B[0] = wf + (size_t)7 * WSZ;   // pv
    p4.C[0] = out;
    tgemm_f16<false, false><<<dim3(8, 16, 1), 256, GEMM_SMEM_BN>>>(p4, SEQ, HID, NTOK);
}